// round 3
// baseline (speedup 1.0000x reference)
#include <cuda_runtime.h>
#include <cuda_bf16.h>
#include <math.h>

#define NNODE 650
#define NPAD  672            // 650 padded to multiple of 32
#define FDIM  512
#define NE    150000
#define ET    150650

// ---------------- device scratch ----------------
__device__ float g_x[NNODE * FDIM];      // layer-1 output / layer-2 input
__device__ float g_h[NNODE * FDIM];      // h = x @ W
__device__ float g_A[NPAD * NPAD];       // dense alpha-numerator matrix [dst][src], zero-padded
__device__ float g_als[NNODE];
__device__ float g_ald[NNODE];
__device__ float g_sum[NNODE];
__device__ float g_M;                     // global max of g_als

__device__ __forceinline__ float leaky02(float x) { return fmaxf(x, 0.2f * x); }

// ---------------- prep: zero A, sum, als, ald ----------------
__global__ void prep_kernel() {
    int i = blockIdx.x * 256 + threadIdx.x;
    if (i < NPAD * NPAD) g_A[i] = 0.f;
    if (i < NNODE) { g_sum[i] = 0.f; g_als[i] = 0.f; g_ald[i] = 0.f; }
}

// ---------------- GEMM 1: h = X @ W, epilogue computes attention logits -------
// use_gx == 0: X rows [0,400) from xs, rows [400,650) from xt
// use_gx == 1: X = g_x (device symbol, accessed from device code only)
// BM=32 BN=64 BK=32, 256 threads, 2x4 microtile
__global__ __launch_bounds__(256) void gemm_xw_kernel(const float* __restrict__ xs,
                                                      const float* __restrict__ xt,
                                                      int use_gx,
                                                      const float* __restrict__ W,
                                                      const float* __restrict__ avs,
                                                      const float* __restrict__ avd) {
    __shared__ float As[32][33];
    __shared__ float Bs[32][64];
    const int tid = threadIdx.x;
    const int bm = blockIdx.y * 32;
    const int bn = blockIdx.x * 64;
    const int tr = tid >> 4, tc = tid & 15;
    const int arow = tid >> 3, acol = (tid & 7) * 4;
    const int brow = tid >> 4, bcol = (tid & 15) * 4;

    // resolve this thread's A-row base pointer once
    const float* abase = nullptr;
    {
        int gr = bm + arow;
        if (gr < NNODE) {
            if (use_gx)          abase = g_x + gr * FDIM;
            else if (gr < 400)   abase = xs + gr * FDIM;
            else                 abase = xt + (gr - 400) * FDIM;
        }
    }

    float acc[2][4] = {{0,0,0,0},{0,0,0,0}};

    for (int k0 = 0; k0 < FDIM; k0 += 32) {
        float4 av = make_float4(0.f,0.f,0.f,0.f);
        if (abase) av = *(const float4*)(abase + k0 + acol);
        As[acol+0][arow]=av.x; As[acol+1][arow]=av.y;
        As[acol+2][arow]=av.z; As[acol+3][arow]=av.w;

        *(float4*)&Bs[brow][bcol]      = *(const float4*)(W + (k0+brow)     *FDIM + bn + bcol);
        *(float4*)&Bs[brow+16][bcol]   = *(const float4*)(W + (k0+brow+16)  *FDIM + bn + bcol);
        __syncthreads();
#pragma unroll
        for (int k = 0; k < 32; k++) {
            float a0 = As[k][tr*2+0], a1 = As[k][tr*2+1];
            float4 b = *(const float4*)&Bs[k][tc*4];
            acc[0][0]+=a0*b.x; acc[0][1]+=a0*b.y; acc[0][2]+=a0*b.z; acc[0][3]+=a0*b.w;
            acc[1][0]+=a1*b.x; acc[1][1]+=a1*b.y; acc[1][2]+=a1*b.z; acc[1][3]+=a1*b.w;
        }
        __syncthreads();
    }

    const int r0 = bm + tr*2, r1 = r0 + 1;
    if (r0 < NNODE)
        *(float4*)(&g_h[r0*FDIM + bn + tc*4]) = make_float4(acc[0][0],acc[0][1],acc[0][2],acc[0][3]);
    if (r1 < NNODE)
        *(float4*)(&g_h[r1*FDIM + bn + tc*4]) = make_float4(acc[1][0],acc[1][1],acc[1][2],acc[1][3]);

    // epilogue: partial logits for this block's 64-column slice
    float4 va = *(const float4*)(avs + bn + tc*4);
    float4 vd = *(const float4*)(avd + bn + tc*4);
    float sa0 = acc[0][0]*va.x + acc[0][1]*va.y + acc[0][2]*va.z + acc[0][3]*va.w;
    float sd0 = acc[0][0]*vd.x + acc[0][1]*vd.y + acc[0][2]*vd.z + acc[0][3]*vd.w;
    float sa1 = acc[1][0]*va.x + acc[1][1]*va.y + acc[1][2]*va.z + acc[1][3]*va.w;
    float sd1 = acc[1][0]*vd.x + acc[1][1]*vd.y + acc[1][2]*vd.z + acc[1][3]*vd.w;
#pragma unroll
    for (int o = 8; o > 0; o >>= 1) {
        sa0 += __shfl_down_sync(0xffffffffu, sa0, o, 16);
        sd0 += __shfl_down_sync(0xffffffffu, sd0, o, 16);
        sa1 += __shfl_down_sync(0xffffffffu, sa1, o, 16);
        sd1 += __shfl_down_sync(0xffffffffu, sd1, o, 16);
    }
    if (tc == 0) {
        if (r0 < NNODE) { atomicAdd(&g_als[r0], sa0); atomicAdd(&g_ald[r0], sd0); }
        if (r1 < NNODE) { atomicAdd(&g_als[r1], sa1); atomicAdd(&g_ald[r1], sd1); }
    }
}

// ---------------- global max of als ----------------
__global__ void redmax_kernel() {
    __shared__ float r[256];
    int t = threadIdx.x;
    float m = -1e30f;
    for (int i = t; i < NNODE; i += 256) m = fmaxf(m, g_als[i]);
    r[t] = m; __syncthreads();
    for (int s = 128; s > 0; s >>= 1) { if (t < s) r[t] = fmaxf(r[t], r[t+s]); __syncthreads(); }
    if (t == 0) g_M = r[0];
}

// ---------------- edge scatter: A[d][s] += p, sum[d] += p ----------------
__global__ void scatter_kernel(const int* __restrict__ ei) {
    int i = blockIdx.x * 256 + threadIdx.x;
    if (i >= ET) return;
    int s, d;
    if (i < NE) { s = ei[i]; d = ei[NE + i]; }
    else        { s = i - NE; d = i - NE; }
    float als = g_als[s], ald = g_ald[d];
    float e  = leaky02(als + ald);
    float mp = leaky02(g_M + ald);        // valid softmax shift (>= true segment max)
    float p  = expf(e - mp);
    atomicAdd(&g_A[d * NPAD + s], p);
    atomicAdd(&g_sum[d], p);
}

// ---------------- GEMM 2: out = (A @ h) * inv_sum + b, activation -> g_x ------
// act: 0 = relu, 1 = leaky 0.01
__global__ __launch_bounds__(256) void gemm_ah_kernel(const float* __restrict__ bias, int act) {
    __shared__ float As[32][33];
    __shared__ float Bs[32][64];
    const int tid = threadIdx.x;
    const int bm = blockIdx.y * 32;
    const int bn = blockIdx.x * 64;
    const int tr = tid >> 4, tc = tid & 15;
    const int arow = tid >> 3, acol = (tid & 7) * 4;
    const int brow = tid >> 4, bcol = (tid & 15) * 4;

    float acc[2][4] = {{0,0,0,0},{0,0,0,0}};

    for (int k0 = 0; k0 < NPAD; k0 += 32) {
        float4 av = *(const float4*)(&g_A[(bm + arow) * NPAD + k0 + acol]);
        As[acol+0][arow]=av.x; As[acol+1][arow]=av.y;
        As[acol+2][arow]=av.z; As[acol+3][arow]=av.w;

        int kr0 = k0 + brow, kr1 = k0 + brow + 16;
        float4 b0 = make_float4(0.f,0.f,0.f,0.f), b1 = b0;
        if (kr0 < NNODE) b0 = *(const float4*)(&g_h[kr0*FDIM + bn + bcol]);
        if (kr1 < NNODE) b1 = *(const float4*)(&g_h[kr1*FDIM + bn + bcol]);
        *(float4*)&Bs[brow][bcol]    = b0;
        *(float4*)&Bs[brow+16][bcol] = b1;
        __syncthreads();
#pragma unroll
        for (int k = 0; k < 32; k++) {
            float a0 = As[k][tr*2+0], a1 = As[k][tr*2+1];
            float4 b = *(const float4*)&Bs[k][tc*4];
            acc[0][0]+=a0*b.x; acc[0][1]+=a0*b.y; acc[0][2]+=a0*b.z; acc[0][3]+=a0*b.w;
            acc[1][0]+=a1*b.x; acc[1][1]+=a1*b.y; acc[1][2]+=a1*b.z; acc[1][3]+=a1*b.w;
        }
        __syncthreads();
    }

    float4 bv = *(const float4*)(bias + bn + tc*4);
    const float bb[4] = {bv.x, bv.y, bv.z, bv.w};
#pragma unroll
    for (int rr = 0; rr < 2; rr++) {
        int r = bm + tr*2 + rr;
        if (r >= NNODE) continue;
        float inv = 1.f / (g_sum[r] + 1e-16f);
        float4 o;
        float v0 = acc[rr][0]*inv + bb[0];
        float v1 = acc[rr][1]*inv + bb[1];
        float v2 = acc[rr][2]*inv + bb[2];
        float v3 = acc[rr][3]*inv + bb[3];
        if (act == 0) {
            o = make_float4(fmaxf(v0,0.f), fmaxf(v1,0.f), fmaxf(v2,0.f), fmaxf(v3,0.f));
        } else {
            o = make_float4(v0>0.f?v0:0.01f*v0, v1>0.f?v1:0.01f*v1,
                            v2>0.f?v2:0.01f*v2, v3>0.f?v3:0.01f*v3);
        }
        *(float4*)(&g_x[r*FDIM + bn + tc*4]) = o;
    }
}

// ---------------- fc + sigmoid ----------------
__global__ __launch_bounds__(256) void fc_kernel(const float* __restrict__ fcw,
                                                 const float* __restrict__ fcb,
                                                 float* __restrict__ out) {
    int j = blockIdx.x;
    int t = threadIdx.x;
    float acc = 0.f;
    const float* y = &g_x[j * NNODE];
    for (int k = t; k < NNODE; k += 256) acc += y[k] * fcw[k];
    __shared__ float r[256];
    r[t] = acc; __syncthreads();
    for (int s = 128; s > 0; s >>= 1) { if (t < s) r[t] += r[t+s]; __syncthreads(); }
    if (t == 0) out[j] = 1.f / (1.f + expf(-(r[0] + fcb[0])));
}

// ---------------- launch ----------------
extern "C" void kernel_launch(void* const* d_in, const int* in_sizes, int n_in,
                              void* d_out, int out_size) {
    const float* x_s = (const float*)d_in[0];
    const float* x_t = (const float*)d_in[1];
    const int*   ei  = (const int*)  d_in[2];
    const float* W1  = (const float*)d_in[5];
    const float* as1 = (const float*)d_in[6];
    const float* ad1 = (const float*)d_in[7];
    const float* b1  = (const float*)d_in[8];
    const float* W4  = (const float*)d_in[9];
    const float* as4 = (const float*)d_in[10];
    const float* ad4 = (const float*)d_in[11];
    const float* b4  = (const float*)d_in[12];
    const float* fcw = (const float*)d_in[13];
    const float* fcb = (const float*)d_in[14];
    float* out = (float*)d_out;

    dim3 ggrid(FDIM / 64, NPAD / 32);            // 8 x 21
    int prep_blocks = (NPAD * NPAD + 255) / 256; // 1764
    int scat_blocks = (ET + 255) / 256;          // 589

    // ---- layer 1 ----
    prep_kernel<<<prep_blocks, 256>>>();
    gemm_xw_kernel<<<ggrid, 256>>>(x_s, x_t, 0, W1, as1, ad1);
    redmax_kernel<<<1, 256>>>();
    scatter_kernel<<<scat_blocks, 256>>>(ei);
    gemm_ah_kernel<<<ggrid, 256>>>(b1, 0);       // relu

    // ---- layer 2 ----
    prep_kernel<<<prep_blocks, 256>>>();
    gemm_xw_kernel<<<ggrid, 256>>>(x_s, x_t, 1, W4, as4, ad4);   // reads g_x internally
    redmax_kernel<<<1, 256>>>();
    scatter_kernel<<<scat_blocks, 256>>>(ei);
    gemm_ah_kernel<<<ggrid, 256>>>(b4, 1);       // leaky 0.01

    // ---- fc ----
    fc_kernel<<<FDIM, 256>>>(fcw, fcb, out);
}